// round 2
// baseline (speedup 1.0000x reference)
#include <cuda_runtime.h>

#define H_IMG 256
#define W_IMG 256
#define B_SZ 8
#define NPIX (B_SZ * H_IMG * W_IMG) /* 524288 */
#define BN_EPS 1e-5f

// -------- scratch (allocation-free: __device__ globals) --------
__device__ float g_y1[B_SZ * 32 * H_IMG * W_IMG];   // conv1 raw output (67 MB)
__device__ float g_y2[B_SZ * 64 * H_IMG * W_IMG];   // conv2 raw output (134 MB)
__device__ float g_w1t[3 * 9 * 32];                 // transposed weights [cin*9][cout]
__device__ float g_w2t[32 * 9 * 64];
__device__ float g_w3t[64 * 9 * 128];
__device__ float g_s1[2 * 32];                      // [sum(32), sumsq(32)]
__device__ float g_s2[2 * 64];
__device__ float g_s3[2 * 128];

// ---- packed fp32x2 helpers (sm_100+; FFMA2 is PTX-only, ptxas never auto-emits) ----
__device__ __forceinline__ unsigned long long fma2(unsigned long long a,
                                                   unsigned long long b,
                                                   unsigned long long c) {
    unsigned long long d;
    asm("fma.rn.f32x2 %0, %1, %2, %3;" : "=l"(d) : "l"(a), "l"(b), "l"(c));
    return d;
}
__device__ __forceinline__ unsigned long long pack2(float x) {
    unsigned long long r;
    unsigned int u = __float_as_uint(x);
    asm("mov.b64 %0, {%1, %1};" : "=l"(r) : "r"(u));
    return r;
}
__device__ __forceinline__ void unpack2(unsigned long long p, float& lo, float& hi) {
    unsigned int a, b;
    asm("mov.b64 {%0, %1}, %2;" : "=r"(a), "=r"(b) : "l"(p));
    lo = __uint_as_float(a);
    hi = __uint_as_float(b);
}

__global__ void zero_stats_kernel() {
    int i = threadIdx.x;
    if (i < 64)  g_s1[i] = 0.f;
    if (i < 128) g_s2[i] = 0.f;
    if (i < 256) g_s3[i] = 0.f;
}

// w (OIHW) -> wt[(ci*9+t)*COUT + o]
template <int LAYER>
__global__ void transpose_w_kernel(const float* __restrict__ w) {
    constexpr int CIN  = (LAYER == 1) ? 3  : (LAYER == 2 ? 32 : 64);
    constexpr int COUT = (LAYER == 1) ? 32 : (LAYER == 2 ? 64 : 128);
    float* wt = (LAYER == 1) ? g_w1t : (LAYER == 2 ? g_w2t : g_w3t);
    int idx = blockIdx.x * blockDim.x + threadIdx.x;
    if (idx >= CIN * 9 * COUT) return;
    int o = idx % COUT;
    int r = idx / COUT;       // ci*9 + t
    int ci = r / 9, t = r % 9;
    wt[idx] = w[(o * CIN + ci) * 9 + t];
}

// Direct tiled conv: 16x16 spatial tile, 32 couts per block, CIN chunked in smem.
// Applies BN+leakyReLU of the previous layer on load (padding = 0 post-activation).
// Accumulates per-channel sum / sumsq of (conv + bias) into out_stats.
// Inner loop uses packed fma.rn.f32x2: 16 FFMA2 instead of 32 FFMA per (cin,tap).
template <int LAYER, int CIN, int CHUNK, int COUT, bool HAS_BN, bool WRITE>
__global__ __launch_bounds__(256) void conv_kernel(
    const float* __restrict__ image,      // only used when LAYER==1
    const float* __restrict__ in_gamma,   // BN params of previous layer
    const float* __restrict__ in_beta,
    const float* __restrict__ bias)       // this layer's conv bias
{
    const float* in = (LAYER == 1) ? image
                    : (LAYER == 2) ? (const float*)g_y1 : (const float*)g_y2;
    const float* wt = (LAYER == 1) ? (const float*)g_w1t
                    : (LAYER == 2) ? (const float*)g_w2t : (const float*)g_w3t;
    const float* in_stats = (LAYER == 2) ? (const float*)g_s1 : (const float*)g_s2;
    float* out       = (LAYER == 1) ? (float*)g_y1 : (float*)g_y2;
    float* out_stats = (LAYER == 1) ? g_s1 : (LAYER == 2 ? g_s2 : g_s3);

    constexpr int NG = COUT / 32;
    const int tx = threadIdx.x & 15;
    const int ty = threadIdx.x >> 4;
    const int tile_x = blockIdx.x * 16;
    const int tile_y = blockIdx.y * 16;
    const int g = blockIdx.z % NG;
    const int b = blockIdx.z / NG;

    __shared__ float s_in[CHUNK][18][18];
    __shared__ float s_w[CHUNK * 9 * 32];
    __shared__ float s_scale[CHUNK], s_shift[CHUNK];

    unsigned long long acc[16];   // 16 packed pairs = 32 fp32 accumulators
#pragma unroll
    for (int q = 0; q < 16; q++) acc[q] = 0ull;

    for (int c0 = 0; c0 < CIN; c0 += CHUNK) {
        __syncthreads();   // protect previous iteration's smem reads
        if (HAS_BN) {
            if (threadIdx.x < CHUNK) {
                int c = c0 + threadIdx.x;
                float mean = in_stats[c] * (1.f / NPIX);
                float var  = in_stats[CIN + c] * (1.f / NPIX) - mean * mean;
                float is   = rsqrtf(var + BN_EPS);
                float sc   = in_gamma[c] * is;
                s_scale[threadIdx.x] = sc;
                s_shift[threadIdx.x] = in_beta[c] - mean * sc;
            }
            __syncthreads();
        }
        // input tile: (CHUNK)x18x18, zero padded, BN+lrelu applied in-range
        for (int i = threadIdx.x; i < CHUNK * 18 * 18; i += 256) {
            int c  = i / 324;
            int r  = i - c * 324;
            int yy = r / 18;
            int xx = r - yy * 18;
            int gy = tile_y + yy - 1, gx = tile_x + xx - 1;
            float v = 0.f;
            if (gy >= 0 && gy < H_IMG && gx >= 0 && gx < W_IMG) {
                v = in[((b * CIN + c0 + c) * H_IMG + gy) * W_IMG + gx];
                if (HAS_BN) {
                    v = v * s_scale[c] + s_shift[c];
                    v = v > 0.f ? v : 0.01f * v;
                }
            }
            s_in[c][yy][xx] = v;
        }
        // weights: coalesced global (runs of 32 couts) + conflict-free smem store
        for (int i = threadIdx.x; i < CHUNK * 9 * 32; i += 256) {
            int rt = i >> 5;   // c*9 + t (relative)
            int o  = i & 31;
            s_w[i] = wt[(c0 * 9 + rt) * COUT + g * 32 + o];
        }
        __syncthreads();

#pragma unroll 1
        for (int c = 0; c < CHUNK; c++) {
#pragma unroll
            for (int t = 0; t < 9; t++) {
                unsigned long long xx = pack2(s_in[c][ty + t / 3][tx + t % 3]);
                const ulonglong2* wv = (const ulonglong2*)&s_w[(c * 9 + t) * 32];
#pragma unroll
                for (int q = 0; q < 8; q++) {
                    ulonglong2 w2 = wv[q];                 // LDS.128 = 4 weights
                    acc[2 * q]     = fma2(xx, w2.x, acc[2 * q]);
                    acc[2 * q + 1] = fma2(xx, w2.y, acc[2 * q + 1]);
                }
            }
        }
    }

    float accs[32];
#pragma unroll
    for (int q = 0; q < 16; q++) unpack2(acc[q], accs[2 * q], accs[2 * q + 1]);
#pragma unroll
    for (int o = 0; o < 32; o++) accs[o] += bias[g * 32 + o];

    if (WRITE) {
        int gy = tile_y + ty, gx = tile_x + tx;
        int base = ((b * COUT + g * 32) * H_IMG + gy) * W_IMG + gx;
#pragma unroll
        for (int o = 0; o < 32; o++) out[base + o * (H_IMG * W_IMG)] = accs[o];
    }

    // per-channel sum / sumsq: warp shuffle reduce, one atomic per warp per channel
    int lane = threadIdx.x & 31;
#pragma unroll
    for (int o = 0; o < 32; o++) {
        float v = accs[o];
        float v2 = v * v;
#pragma unroll
        for (int s = 16; s > 0; s >>= 1) {
            v  += __shfl_down_sync(0xffffffffu, v, s);
            v2 += __shfl_down_sync(0xffffffffu, v2, s);
        }
        if (lane == 0) {
            atomicAdd(&out_stats[g * 32 + o], v);
            atomicAdd(&out_stats[COUT + g * 32 + o], v2);
        }
    }
}

// Gather the three 7x7 patch sets (exact pixel copies). Output order:
// anchors [0,1176) | positives [1176,2352) | negatives [2352,3528)
__global__ void patch_kernel(const float* __restrict__ image,
                             const int* __restrict__ a_xy,
                             const int* __restrict__ p_xy,
                             const int* __restrict__ n_xy,
                             float* __restrict__ out)
{
    int idx = blockIdx.x * blockDim.x + threadIdx.x;
    if (idx >= 3 * B_SZ * 3 * 7 * 7) return;
    int which = idx / 1176;
    int r  = idx % 1176;
    int b  = r / 147;
    int r2 = r % 147;
    int c  = r2 / 49;
    int p  = r2 % 49;
    int dy = p / 7, dx = p % 7;
    const int* xy = (which == 0) ? a_xy : (which == 1 ? p_xy : n_xy);
    int row = xy[b * 64 + 62];   // [:, -1, 0]  (last of 32 patches)
    int col = xy[b * 64 + 63];   // [:, -1, 1]
    out[idx] = image[((b * 3 + c) * H_IMG + (row - 3 + dy)) * W_IMG + (col - 3 + dx)];
}

// Recompute z3 at the 8 gather points (reference uses n_xy here), apply BN3+lrelu.
__global__ void encode_kernel(const int* __restrict__ n_xy,
                              const float* __restrict__ bn2_g, const float* __restrict__ bn2_b,
                              const float* __restrict__ conv3_b,
                              const float* __restrict__ bn3_g, const float* __restrict__ bn3_b,
                              float* __restrict__ out)
{
    int b = blockIdx.x;
    int o = threadIdx.x;   // 128 threads = 128 output channels
    __shared__ float s_z2[64 * 9];
    int row = n_xy[b * 64 + 62];
    int col = n_xy[b * 64 + 63];
    // coords are in [3,252] -> the 3x3 neighborhood is interior, no padding needed
    for (int i = threadIdx.x; i < 576; i += 128) {
        int c = i / 9, p = i % 9;
        int ky = p / 3 - 1, kx = p % 3 - 1;
        float mean = g_s2[c] * (1.f / NPIX);
        float var  = g_s2[64 + c] * (1.f / NPIX) - mean * mean;
        float is   = rsqrtf(var + BN_EPS);
        float sc   = bn2_g[c] * is;
        float sh   = bn2_b[c] - mean * sc;
        float v = g_y2[((b * 64 + c) * H_IMG + row + ky) * W_IMG + col + kx];
        v = v * sc + sh;
        v = v > 0.f ? v : 0.01f * v;
        s_z2[i] = v;
    }
    __syncthreads();
    float acc = conv3_b[o];
    for (int i = 0; i < 576; i++)
        acc = fmaf(s_z2[i], g_w3t[i * 128 + o], acc);
    float mean = g_s3[o] * (1.f / NPIX);
    float var  = g_s3[128 + o] * (1.f / NPIX) - mean * mean;
    float is   = rsqrtf(var + BN_EPS);
    float v = (acc - mean) * is * bn3_g[o] + bn3_b[o];
    v = v > 0.f ? v : 0.01f * v;
    out[3528 + b * 128 + o] = v;
}

extern "C" void kernel_launch(void* const* d_in, const int* in_sizes, int n_in,
                              void* d_out, int out_size) {
    const float* image = (const float*)d_in[0];
    const int*   a_xy  = (const int*)d_in[1];
    const int*   p_xy  = (const int*)d_in[2];
    const int*   n_xy  = (const int*)d_in[3];
    const float* w1  = (const float*)d_in[4];
    const float* b1  = (const float*)d_in[5];
    const float* g1  = (const float*)d_in[6];
    const float* be1 = (const float*)d_in[7];
    const float* w2  = (const float*)d_in[8];
    const float* b2  = (const float*)d_in[9];
    const float* g2  = (const float*)d_in[10];
    const float* be2 = (const float*)d_in[11];
    const float* w3  = (const float*)d_in[12];
    const float* b3  = (const float*)d_in[13];
    const float* g3  = (const float*)d_in[14];
    const float* be3 = (const float*)d_in[15];
    // d_in[16]=recon_w, d_in[17]=recon_b : dead in the reference, unused.
    float* out = (float*)d_out;

    zero_stats_kernel<<<1, 256>>>();
    transpose_w_kernel<1><<<(3 * 9 * 32 + 255) / 256, 256>>>(w1);
    transpose_w_kernel<2><<<(32 * 9 * 64 + 255) / 256, 256>>>(w2);
    transpose_w_kernel<3><<<(64 * 9 * 128 + 255) / 256, 256>>>(w3);

    conv_kernel<1, 3, 3, 32, false, true><<<dim3(16, 16, 8), 256>>>(image, nullptr, nullptr, b1);
    conv_kernel<2, 32, 8, 64, true, true><<<dim3(16, 16, 16), 256>>>(nullptr, g1, be1, b2);
    conv_kernel<3, 64, 8, 128, true, false><<<dim3(16, 16, 32), 256>>>(nullptr, g2, be2, b3);

    patch_kernel<<<14, 256>>>(image, a_xy, p_xy, n_xy, out);
    encode_kernel<<<8, 128>>>(n_xy, g2, be2, b3, g3, be3, out);
}

// round 3
// speedup vs baseline: 1.7796x; 1.7796x over previous
#include <cuda_runtime.h>

#define H_IMG 256
#define W_IMG 256
#define B_SZ 8
#define NPIX (B_SZ * H_IMG * W_IMG) /* 524288 */
#define BN_EPS 1e-5f

// -------- scratch (allocation-free: __device__ globals) --------
__device__ float g_y1[B_SZ * 32 * H_IMG * W_IMG];   // conv1 raw output (67 MB)
__device__ float g_y2[B_SZ * 64 * H_IMG * W_IMG];   // conv2 raw output (134 MB)
__device__ float g_w1t[3 * 9 * 32];                 // transposed weights [cin*9][cout]
__device__ float g_w2t[32 * 9 * 64];
__device__ float g_w3t[64 * 9 * 128];
__device__ float g_s1[2 * 32];                      // [sum(32), sumsq(32)]
__device__ float g_s2[2 * 64];
__device__ float g_s3[2 * 128];

__global__ void zero_stats_kernel() {
    int i = threadIdx.x;
    if (i < 64)  g_s1[i] = 0.f;
    if (i < 128) g_s2[i] = 0.f;
    if (i < 256) g_s3[i] = 0.f;
}

// w (OIHW) -> wt[(ci*9+t)*COUT + o]
template <int LAYER>
__global__ void transpose_w_kernel(const float* __restrict__ w) {
    constexpr int CIN  = (LAYER == 1) ? 3  : (LAYER == 2 ? 32 : 64);
    constexpr int COUT = (LAYER == 1) ? 32 : (LAYER == 2 ? 64 : 128);
    float* wt = (LAYER == 1) ? g_w1t : (LAYER == 2 ? g_w2t : g_w3t);
    int idx = blockIdx.x * blockDim.x + threadIdx.x;
    if (idx >= CIN * 9 * COUT) return;
    int o = idx % COUT;
    int r = idx / COUT;       // ci*9 + t
    int ci = r / 9, t = r % 9;
    wt[idx] = w[(o * CIN + ci) * 9 + t];
}

// Direct tiled conv: 16(w) x 32(h) spatial tile, 2 pixels per thread, 32 couts
// per block, CIN chunked in smem. Applies BN+leakyReLU of the previous layer on
// load (padding = 0 post-activation). Accumulates per-channel sum/sumsq of
// (conv + bias) into out_stats.
template <int LAYER, int CIN, int CHUNK, int COUT, bool HAS_BN, bool WRITE>
__global__ __launch_bounds__(256) void conv_kernel(
    const float* __restrict__ image,      // only used when LAYER==1
    const float* __restrict__ in_gamma,   // BN params of previous layer
    const float* __restrict__ in_beta,
    const float* __restrict__ bias)       // this layer's conv bias
{
    const float* in = (LAYER == 1) ? image
                    : (LAYER == 2) ? (const float*)g_y1 : (const float*)g_y2;
    const float* wt = (LAYER == 1) ? (const float*)g_w1t
                    : (LAYER == 2) ? (const float*)g_w2t : (const float*)g_w3t;
    const float* in_stats = (LAYER == 2) ? (const float*)g_s1 : (const float*)g_s2;
    float* out       = (LAYER == 1) ? (float*)g_y1 : (float*)g_y2;
    float* out_stats = (LAYER == 1) ? g_s1 : (LAYER == 2 ? g_s2 : g_s3);

    constexpr int NG = COUT / 32;
    const int tx = threadIdx.x & 15;
    const int ty = threadIdx.x >> 4;
    const int tile_x = blockIdx.x * 16;
    const int tile_y = blockIdx.y * 32;          // 32-row tile
    const int g = blockIdx.z % NG;
    const int b = blockIdx.z / NG;

    __shared__ float s_in[CHUNK][34][18];        // 32+2 halo rows, 16+2 halo cols
    __shared__ float s_w[CHUNK * 9 * 32];
    __shared__ float s_scale[CHUNK], s_shift[CHUNK];

    float acc0[32], acc1[32];
#pragma unroll
    for (int o = 0; o < 32; o++) { acc0[o] = 0.f; acc1[o] = 0.f; }

    for (int c0 = 0; c0 < CIN; c0 += CHUNK) {
        __syncthreads();   // protect previous iteration's smem reads
        if (HAS_BN) {
            if (threadIdx.x < CHUNK) {
                int c = c0 + threadIdx.x;
                float mean = in_stats[c] * (1.f / NPIX);
                float var  = in_stats[CIN + c] * (1.f / NPIX) - mean * mean;
                float is   = rsqrtf(var + BN_EPS);
                float sc   = in_gamma[c] * is;
                s_scale[threadIdx.x] = sc;
                s_shift[threadIdx.x] = in_beta[c] - mean * sc;
            }
            __syncthreads();
        }
        // input tile: (CHUNK)x34x18, zero padded, BN+lrelu applied in-range
        for (int i = threadIdx.x; i < CHUNK * 34 * 18; i += 256) {
            int c  = i / (34 * 18);
            int r  = i - c * (34 * 18);
            int yy = r / 18;
            int xx = r - yy * 18;
            int gy = tile_y + yy - 1, gx = tile_x + xx - 1;
            float v = 0.f;
            if (gy >= 0 && gy < H_IMG && gx >= 0 && gx < W_IMG) {
                v = in[((b * CIN + c0 + c) * H_IMG + gy) * W_IMG + gx];
                if (HAS_BN) {
                    v = v * s_scale[c] + s_shift[c];
                    v = v > 0.f ? v : 0.01f * v;
                }
            }
            s_in[c][yy][xx] = v;
        }
        // weights: coalesced global (runs of 32 couts) + conflict-free smem store
        for (int i = threadIdx.x; i < CHUNK * 9 * 32; i += 256) {
            int rt = i >> 5;   // c*9 + t (relative)
            int o  = i & 31;
            s_w[i] = wt[(c0 * 9 + rt) * COUT + g * 32 + o];
        }
        __syncthreads();

#pragma unroll 1
        for (int c = 0; c < CHUNK; c++) {
#pragma unroll
            for (int t = 0; t < 9; t++) {
                float x0 = s_in[c][ty      + t / 3][tx + t % 3];
                float x1 = s_in[c][ty + 16 + t / 3][tx + t % 3];
                const float4* wv = (const float4*)&s_w[(c * 9 + t) * 32];
#pragma unroll
                for (int o4 = 0; o4 < 8; o4++) {
                    float4 w4 = wv[o4];
                    acc0[o4 * 4 + 0] = fmaf(x0, w4.x, acc0[o4 * 4 + 0]);
                    acc0[o4 * 4 + 1] = fmaf(x0, w4.y, acc0[o4 * 4 + 1]);
                    acc0[o4 * 4 + 2] = fmaf(x0, w4.z, acc0[o4 * 4 + 2]);
                    acc0[o4 * 4 + 3] = fmaf(x0, w4.w, acc0[o4 * 4 + 3]);
                    acc1[o4 * 4 + 0] = fmaf(x1, w4.x, acc1[o4 * 4 + 0]);
                    acc1[o4 * 4 + 1] = fmaf(x1, w4.y, acc1[o4 * 4 + 1]);
                    acc1[o4 * 4 + 2] = fmaf(x1, w4.z, acc1[o4 * 4 + 2]);
                    acc1[o4 * 4 + 3] = fmaf(x1, w4.w, acc1[o4 * 4 + 3]);
                }
            }
        }
    }

#pragma unroll
    for (int o = 0; o < 32; o++) {
        float bv = bias[g * 32 + o];
        acc0[o] += bv;
        acc1[o] += bv;
    }

    if (WRITE) {
        int gx = tile_x + tx;
        int base0 = ((b * COUT + g * 32) * H_IMG + tile_y + ty)      * W_IMG + gx;
        int base1 = ((b * COUT + g * 32) * H_IMG + tile_y + ty + 16) * W_IMG + gx;
#pragma unroll
        for (int o = 0; o < 32; o++) {
            out[base0 + o * (H_IMG * W_IMG)] = acc0[o];
            out[base1 + o * (H_IMG * W_IMG)] = acc1[o];
        }
    }

    // per-channel sum / sumsq over BOTH pixels: warp shuffle reduce,
    // one atomic per warp per channel
    int lane = threadIdx.x & 31;
#pragma unroll
    for (int o = 0; o < 32; o++) {
        float v  = acc0[o] + acc1[o];
        float v2 = acc0[o] * acc0[o] + acc1[o] * acc1[o];
#pragma unroll
        for (int s = 16; s > 0; s >>= 1) {
            v  += __shfl_down_sync(0xffffffffu, v, s);
            v2 += __shfl_down_sync(0xffffffffu, v2, s);
        }
        if (lane == 0) {
            atomicAdd(&out_stats[g * 32 + o], v);
            atomicAdd(&out_stats[COUT + g * 32 + o], v2);
        }
    }
}

// Gather the three 7x7 patch sets (exact pixel copies). Output order:
// anchors [0,1176) | positives [1176,2352) | negatives [2352,3528)
__global__ void patch_kernel(const float* __restrict__ image,
                             const int* __restrict__ a_xy,
                             const int* __restrict__ p_xy,
                             const int* __restrict__ n_xy,
                             float* __restrict__ out)
{
    int idx = blockIdx.x * blockDim.x + threadIdx.x;
    if (idx >= 3 * B_SZ * 3 * 7 * 7) return;
    int which = idx / 1176;
    int r  = idx % 1176;
    int b  = r / 147;
    int r2 = r % 147;
    int c  = r2 / 49;
    int p  = r2 % 49;
    int dy = p / 7, dx = p % 7;
    const int* xy = (which == 0) ? a_xy : (which == 1 ? p_xy : n_xy);
    int row = xy[b * 64 + 62];   // [:, -1, 0]  (last of 32 patches)
    int col = xy[b * 64 + 63];   // [:, -1, 1]
    out[idx] = image[((b * 3 + c) * H_IMG + (row - 3 + dy)) * W_IMG + (col - 3 + dx)];
}

// Recompute z3 at the 8 gather points (reference uses n_xy here), apply BN3+lrelu.
__global__ void encode_kernel(const int* __restrict__ n_xy,
                              const float* __restrict__ bn2_g, const float* __restrict__ bn2_b,
                              const float* __restrict__ conv3_b,
                              const float* __restrict__ bn3_g, const float* __restrict__ bn3_b,
                              float* __restrict__ out)
{
    int b = blockIdx.x;
    int o = threadIdx.x;   // 128 threads = 128 output channels
    __shared__ float s_z2[64 * 9];
    int row = n_xy[b * 64 + 62];
    int col = n_xy[b * 64 + 63];
    // coords are in [3,252] -> the 3x3 neighborhood is interior, no padding needed
    for (int i = threadIdx.x; i < 576; i += 128) {
        int c = i / 9, p = i % 9;
        int ky = p / 3 - 1, kx = p % 3 - 1;
        float mean = g_s2[c] * (1.f / NPIX);
        float var  = g_s2[64 + c] * (1.f / NPIX) - mean * mean;
        float is   = rsqrtf(var + BN_EPS);
        float sc   = bn2_g[c] * is;
        float sh   = bn2_b[c] - mean * sc;
        float v = g_y2[((b * 64 + c) * H_IMG + row + ky) * W_IMG + col + kx];
        v = v * sc + sh;
        v = v > 0.f ? v : 0.01f * v;
        s_z2[i] = v;
    }
    __syncthreads();
    float acc = conv3_b[o];
    for (int i = 0; i < 576; i++)
        acc = fmaf(s_z2[i], g_w3t[i * 128 + o], acc);
    float mean = g_s3[o] * (1.f / NPIX);
    float var  = g_s3[128 + o] * (1.f / NPIX) - mean * mean;
    float is   = rsqrtf(var + BN_EPS);
    float v = (acc - mean) * is * bn3_g[o] + bn3_b[o];
    v = v > 0.f ? v : 0.01f * v;
    out[3528 + b * 128 + o] = v;
}

extern "C" void kernel_launch(void* const* d_in, const int* in_sizes, int n_in,
                              void* d_out, int out_size) {
    const float* image = (const float*)d_in[0];
    const int*   a_xy  = (const int*)d_in[1];
    const int*   p_xy  = (const int*)d_in[2];
    const int*   n_xy  = (const int*)d_in[3];
    const float* w1  = (const float*)d_in[4];
    const float* b1  = (const float*)d_in[5];
    const float* g1  = (const float*)d_in[6];
    const float* be1 = (const float*)d_in[7];
    const float* w2  = (const float*)d_in[8];
    const float* b2  = (const float*)d_in[9];
    const float* g2  = (const float*)d_in[10];
    const float* be2 = (const float*)d_in[11];
    const float* w3  = (const float*)d_in[12];
    const float* b3  = (const float*)d_in[13];
    const float* g3  = (const float*)d_in[14];
    const float* be3 = (const float*)d_in[15];
    // d_in[16]=recon_w, d_in[17]=recon_b : dead in the reference, unused.
    float* out = (float*)d_out;

    zero_stats_kernel<<<1, 256>>>();
    transpose_w_kernel<1><<<(3 * 9 * 32 + 255) / 256, 256>>>(w1);
    transpose_w_kernel<2><<<(32 * 9 * 64 + 255) / 256, 256>>>(w2);
    transpose_w_kernel<3><<<(64 * 9 * 128 + 255) / 256, 256>>>(w3);

    conv_kernel<1, 3, 3, 32, false, true><<<dim3(16, 8, 8), 256>>>(image, nullptr, nullptr, b1);
    conv_kernel<2, 32, 8, 64, true, true><<<dim3(16, 8, 16), 256>>>(nullptr, g1, be1, b2);
    conv_kernel<3, 64, 8, 128, true, false><<<dim3(16, 8, 32), 256>>>(nullptr, g2, be2, b3);

    patch_kernel<<<14, 256>>>(image, a_xy, p_xy, n_xy, out);
    encode_kernel<<<8, 128>>>(n_xy, g2, be2, b3, g3, be3, out);
}

// round 4
// speedup vs baseline: 1.9808x; 1.1130x over previous
#include <cuda_runtime.h>

#define H_IMG 256
#define W_IMG 256
#define B_SZ 8
#define NPIX (B_SZ * H_IMG * W_IMG) /* 524288 */
#define BN_EPS 1e-5f

// -------- scratch (allocation-free: __device__ globals) --------
__device__ float g_y1[B_SZ * 32 * H_IMG * W_IMG];   // conv1 raw output (67 MB)
__device__ float g_y2[B_SZ * 64 * H_IMG * W_IMG];   // conv2 raw output (134 MB)
__device__ float g_w1t[3 * 9 * 32];                 // transposed weights [cin*9][cout]
__device__ float g_w2t[32 * 9 * 64];
__device__ float g_w3t[64 * 9 * 128];
__device__ float g_s1[2 * 32];                      // [sum(32), sumsq(32)]
__device__ float g_s2[2 * 64];
__device__ float g_s3[2 * 128];

__global__ void zero_stats_kernel() {
    int i = threadIdx.x;
    if (i < 64)  g_s1[i] = 0.f;
    if (i < 128) g_s2[i] = 0.f;
    if (i < 256) g_s3[i] = 0.f;
}

// w (OIHW) -> wt[(ci*9+t)*COUT + o]
template <int LAYER>
__global__ void transpose_w_kernel(const float* __restrict__ w) {
    constexpr int CIN  = (LAYER == 1) ? 3  : (LAYER == 2 ? 32 : 64);
    constexpr int COUT = (LAYER == 1) ? 32 : (LAYER == 2 ? 64 : 128);
    float* wt = (LAYER == 1) ? g_w1t : (LAYER == 2 ? g_w2t : g_w3t);
    int idx = blockIdx.x * blockDim.x + threadIdx.x;
    if (idx >= CIN * 9 * COUT) return;
    int o = idx % COUT;
    int r = idx / COUT;       // ci*9 + t
    int ci = r / 9, t = r % 9;
    wt[idx] = w[(o * CIN + ci) * 9 + t];
}

// Direct tiled conv: 16(w) x 64(h) spatial tile, 4 pixels per thread, 32 couts
// per block, CIN chunked in smem. Applies BN+leakyReLU of the previous layer on
// load (padding = 0 post-activation). Accumulates per-channel sum/sumsq of
// (conv + bias) into out_stats.
template <int LAYER, int CIN, int CHUNK, int COUT, bool HAS_BN, bool WRITE>
__global__ __launch_bounds__(256, 1) void conv_kernel(
    const float* __restrict__ image,      // only used when LAYER==1
    const float* __restrict__ in_gamma,   // BN params of previous layer
    const float* __restrict__ in_beta,
    const float* __restrict__ bias)       // this layer's conv bias
{
    const float* in = (LAYER == 1) ? image
                    : (LAYER == 2) ? (const float*)g_y1 : (const float*)g_y2;
    const float* wt = (LAYER == 1) ? (const float*)g_w1t
                    : (LAYER == 2) ? (const float*)g_w2t : (const float*)g_w3t;
    const float* in_stats = (LAYER == 2) ? (const float*)g_s1 : (const float*)g_s2;
    float* out       = (LAYER == 1) ? (float*)g_y1 : (float*)g_y2;
    float* out_stats = (LAYER == 1) ? g_s1 : (LAYER == 2 ? g_s2 : g_s3);

    constexpr int NG = COUT / 32;
    const int tx = threadIdx.x & 15;
    const int ty = threadIdx.x >> 4;
    const int tile_x = blockIdx.x * 16;
    const int tile_y = blockIdx.y * 64;          // 64-row tile
    const int g = blockIdx.z % NG;
    const int b = blockIdx.z / NG;

    __shared__ float s_in[CHUNK][66][18];        // 64+2 halo rows, 16+2 halo cols
    __shared__ float s_w[CHUNK * 9 * 32];
    __shared__ float s_scale[CHUNK], s_shift[CHUNK];

    float acc0[32], acc1[32], acc2[32], acc3[32];
#pragma unroll
    for (int o = 0; o < 32; o++) { acc0[o] = 0.f; acc1[o] = 0.f; acc2[o] = 0.f; acc3[o] = 0.f; }

    for (int c0 = 0; c0 < CIN; c0 += CHUNK) {
        __syncthreads();   // protect previous iteration's smem reads
        if (HAS_BN) {
            if (threadIdx.x < CHUNK) {
                int c = c0 + threadIdx.x;
                float mean = in_stats[c] * (1.f / NPIX);
                float var  = in_stats[CIN + c] * (1.f / NPIX) - mean * mean;
                float is   = rsqrtf(var + BN_EPS);
                float sc   = in_gamma[c] * is;
                s_scale[threadIdx.x] = sc;
                s_shift[threadIdx.x] = in_beta[c] - mean * sc;
            }
            __syncthreads();
        }
        // input tile: (CHUNK)x66x18, zero padded, BN+lrelu applied in-range
        for (int i = threadIdx.x; i < CHUNK * 66 * 18; i += 256) {
            int c  = i / (66 * 18);
            int r  = i - c * (66 * 18);
            int yy = r / 18;
            int xx = r - yy * 18;
            int gy = tile_y + yy - 1, gx = tile_x + xx - 1;
            float v = 0.f;
            if (gy >= 0 && gy < H_IMG && gx >= 0 && gx < W_IMG) {
                v = in[((b * CIN + c0 + c) * H_IMG + gy) * W_IMG + gx];
                if (HAS_BN) {
                    v = v * s_scale[c] + s_shift[c];
                    v = v > 0.f ? v : 0.01f * v;
                }
            }
            s_in[c][yy][xx] = v;
        }
        // weights: coalesced global (runs of 32 couts) + conflict-free smem store
        for (int i = threadIdx.x; i < CHUNK * 9 * 32; i += 256) {
            int rt = i >> 5;   // c*9 + t (relative)
            int o  = i & 31;
            s_w[i] = wt[(c0 * 9 + rt) * COUT + g * 32 + o];
        }
        __syncthreads();

#pragma unroll 1
        for (int c = 0; c < CHUNK; c++) {
#pragma unroll
            for (int t = 0; t < 9; t++) {
                float x0 = s_in[c][ty      + t / 3][tx + t % 3];
                float x1 = s_in[c][ty + 16 + t / 3][tx + t % 3];
                float x2 = s_in[c][ty + 32 + t / 3][tx + t % 3];
                float x3 = s_in[c][ty + 48 + t / 3][tx + t % 3];
                const float4* wv = (const float4*)&s_w[(c * 9 + t) * 32];
#pragma unroll
                for (int o4 = 0; o4 < 8; o4++) {
                    float4 w4 = wv[o4];
                    acc0[o4 * 4 + 0] = fmaf(x0, w4.x, acc0[o4 * 4 + 0]);
                    acc0[o4 * 4 + 1] = fmaf(x0, w4.y, acc0[o4 * 4 + 1]);
                    acc0[o4 * 4 + 2] = fmaf(x0, w4.z, acc0[o4 * 4 + 2]);
                    acc0[o4 * 4 + 3] = fmaf(x0, w4.w, acc0[o4 * 4 + 3]);
                    acc1[o4 * 4 + 0] = fmaf(x1, w4.x, acc1[o4 * 4 + 0]);
                    acc1[o4 * 4 + 1] = fmaf(x1, w4.y, acc1[o4 * 4 + 1]);
                    acc1[o4 * 4 + 2] = fmaf(x1, w4.z, acc1[o4 * 4 + 2]);
                    acc1[o4 * 4 + 3] = fmaf(x1, w4.w, acc1[o4 * 4 + 3]);
                    acc2[o4 * 4 + 0] = fmaf(x2, w4.x, acc2[o4 * 4 + 0]);
                    acc2[o4 * 4 + 1] = fmaf(x2, w4.y, acc2[o4 * 4 + 1]);
                    acc2[o4 * 4 + 2] = fmaf(x2, w4.z, acc2[o4 * 4 + 2]);
                    acc2[o4 * 4 + 3] = fmaf(x2, w4.w, acc2[o4 * 4 + 3]);
                    acc3[o4 * 4 + 0] = fmaf(x3, w4.x, acc3[o4 * 4 + 0]);
                    acc3[o4 * 4 + 1] = fmaf(x3, w4.y, acc3[o4 * 4 + 1]);
                    acc3[o4 * 4 + 2] = fmaf(x3, w4.z, acc3[o4 * 4 + 2]);
                    acc3[o4 * 4 + 3] = fmaf(x3, w4.w, acc3[o4 * 4 + 3]);
                }
            }
        }
    }

#pragma unroll
    for (int o = 0; o < 32; o++) {
        float bv = bias[g * 32 + o];
        acc0[o] += bv; acc1[o] += bv; acc2[o] += bv; acc3[o] += bv;
    }

    if (WRITE) {
        int gx = tile_x + tx;
        int base = ((b * COUT + g * 32) * H_IMG + tile_y + ty) * W_IMG + gx;
#pragma unroll
        for (int o = 0; o < 32; o++) {
            int p = base + o * (H_IMG * W_IMG);
            out[p]                 = acc0[o];
            out[p + 16 * W_IMG]    = acc1[o];
            out[p + 32 * W_IMG]    = acc2[o];
            out[p + 48 * W_IMG]    = acc3[o];
        }
    }

    // per-channel sum / sumsq over the 4 pixels: warp shuffle reduce,
    // one atomic per warp per channel
    int lane = threadIdx.x & 31;
#pragma unroll
    for (int o = 0; o < 32; o++) {
        float v  = acc0[o] + acc1[o] + acc2[o] + acc3[o];
        float v2 = acc0[o] * acc0[o] + acc1[o] * acc1[o]
                 + acc2[o] * acc2[o] + acc3[o] * acc3[o];
#pragma unroll
        for (int s = 16; s > 0; s >>= 1) {
            v  += __shfl_down_sync(0xffffffffu, v, s);
            v2 += __shfl_down_sync(0xffffffffu, v2, s);
        }
        if (lane == 0) {
            atomicAdd(&out_stats[g * 32 + o], v);
            atomicAdd(&out_stats[COUT + g * 32 + o], v2);
        }
    }
}

// Gather the three 7x7 patch sets (exact pixel copies). Output order:
// anchors [0,1176) | positives [1176,2352) | negatives [2352,3528)
__global__ void patch_kernel(const float* __restrict__ image,
                             const int* __restrict__ a_xy,
                             const int* __restrict__ p_xy,
                             const int* __restrict__ n_xy,
                             float* __restrict__ out)
{
    int idx = blockIdx.x * blockDim.x + threadIdx.x;
    if (idx >= 3 * B_SZ * 3 * 7 * 7) return;
    int which = idx / 1176;
    int r  = idx % 1176;
    int b  = r / 147;
    int r2 = r % 147;
    int c  = r2 / 49;
    int p  = r2 % 49;
    int dy = p / 7, dx = p % 7;
    const int* xy = (which == 0) ? a_xy : (which == 1 ? p_xy : n_xy);
    int row = xy[b * 64 + 62];   // [:, -1, 0]  (last of 32 patches)
    int col = xy[b * 64 + 63];   // [:, -1, 1]
    out[idx] = image[((b * 3 + c) * H_IMG + (row - 3 + dy)) * W_IMG + (col - 3 + dx)];
}

// Recompute z3 at the 8 gather points (reference uses n_xy here), apply BN3+lrelu.
__global__ void encode_kernel(const int* __restrict__ n_xy,
                              const float* __restrict__ bn2_g, const float* __restrict__ bn2_b,
                              const float* __restrict__ conv3_b,
                              const float* __restrict__ bn3_g, const float* __restrict__ bn3_b,
                              float* __restrict__ out)
{
    int b = blockIdx.x;
    int o = threadIdx.x;   // 128 threads = 128 output channels
    __shared__ float s_z2[64 * 9];
    int row = n_xy[b * 64 + 62];
    int col = n_xy[b * 64 + 63];
    // coords are in [3,252] -> the 3x3 neighborhood is interior, no padding needed
    for (int i = threadIdx.x; i < 576; i += 128) {
        int c = i / 9, p = i % 9;
        int ky = p / 3 - 1, kx = p % 3 - 1;
        float mean = g_s2[c] * (1.f / NPIX);
        float var  = g_s2[64 + c] * (1.f / NPIX) - mean * mean;
        float is   = rsqrtf(var + BN_EPS);
        float sc   = bn2_g[c] * is;
        float sh   = bn2_b[c] - mean * sc;
        float v = g_y2[((b * 64 + c) * H_IMG + row + ky) * W_IMG + col + kx];
        v = v * sc + sh;
        v = v > 0.f ? v : 0.01f * v;
        s_z2[i] = v;
    }
    __syncthreads();
    float acc = conv3_b[o];
    for (int i = 0; i < 576; i++)
        acc = fmaf(s_z2[i], g_w3t[i * 128 + o], acc);
    float mean = g_s3[o] * (1.f / NPIX);
    float var  = g_s3[128 + o] * (1.f / NPIX) - mean * mean;
    float is   = rsqrtf(var + BN_EPS);
    float v = (acc - mean) * is * bn3_g[o] + bn3_b[o];
    v = v > 0.f ? v : 0.01f * v;
    out[3528 + b * 128 + o] = v;
}

extern "C" void kernel_launch(void* const* d_in, const int* in_sizes, int n_in,
                              void* d_out, int out_size) {
    const float* image = (const float*)d_in[0];
    const int*   a_xy  = (const int*)d_in[1];
    const int*   p_xy  = (const int*)d_in[2];
    const int*   n_xy  = (const int*)d_in[3];
    const float* w1  = (const float*)d_in[4];
    const float* b1  = (const float*)d_in[5];
    const float* g1  = (const float*)d_in[6];
    const float* be1 = (const float*)d_in[7];
    const float* w2  = (const float*)d_in[8];
    const float* b2  = (const float*)d_in[9];
    const float* g2  = (const float*)d_in[10];
    const float* be2 = (const float*)d_in[11];
    const float* w3  = (const float*)d_in[12];
    const float* b3  = (const float*)d_in[13];
    const float* g3  = (const float*)d_in[14];
    const float* be3 = (const float*)d_in[15];
    // d_in[16]=recon_w, d_in[17]=recon_b : dead in the reference, unused.
    float* out = (float*)d_out;

    zero_stats_kernel<<<1, 256>>>();
    transpose_w_kernel<1><<<(3 * 9 * 32 + 255) / 256, 256>>>(w1);
    transpose_w_kernel<2><<<(32 * 9 * 64 + 255) / 256, 256>>>(w2);
    transpose_w_kernel<3><<<(64 * 9 * 128 + 255) / 256, 256>>>(w3);

    conv_kernel<1, 3, 3, 32, false, true><<<dim3(16, 4, 8), 256>>>(image, nullptr, nullptr, b1);
    conv_kernel<2, 32, 8, 64, true, true><<<dim3(16, 4, 16), 256>>>(nullptr, g1, be1, b2);
    conv_kernel<3, 64, 8, 128, true, false><<<dim3(16, 4, 32), 256>>>(nullptr, g2, be2, b3);

    patch_kernel<<<14, 256>>>(image, a_xy, p_xy, n_xy, out);
    encode_kernel<<<8, 128>>>(n_xy, g2, be2, b3, g3, be3, out);
}